// round 2
// baseline (speedup 1.0000x reference)
#include <cuda_runtime.h>
#include <cuda_bf16.h>
#include <cstdint>

// Problem constants
#define D_EMBED 1024
#define N_HEAD  16
#define DH      64
#define LEN     1024
#define SEQ_S   3072
#define BATCH   2

// Scratch (device globals: allocation-free)
__device__ float g_Q  [BATCH * LEN   * D_EMBED];   // 8 MB
__device__ float g_K  [BATCH * SEQ_S * D_EMBED];   // 24 MB (also reused for attn_out)
__device__ float g_V  [BATCH * SEQ_S * D_EMBED];   // 24 MB
__device__ float g_CTX[BATCH * LEN   * D_EMBED];   // 8 MB

// ---------------------------------------------------------------------------
// NT SGEMM:  C[m,n] = sum_k A[m,k] * W[n,k] + bias[n]
// A row-major (M x 1024), W row-major (N x 1024). BM=BN=128, BK=8, 256 thr,
// 8x8 per thread (4x4 quadrants at +0/+64), float4 global loads, reg prefetch.
// mode: 0 = A1 contiguous rows; 1 = KV concat gather; 2 = read g_CTX
// out_sel: 0 = g_Q, 1 = g_K, 2 = g_V
// ---------------------------------------------------------------------------
__global__ void __launch_bounds__(256) sgemm_nt(
    const float* __restrict__ A1, const float* __restrict__ A2, int mode,
    const float* __restrict__ W,  const float* __restrict__ bias,
    int out_sel, int M)
{
    __shared__ float As[8][132];
    __shared__ float Bs[8][132];

    const int tid = threadIdx.x;
    const int bm  = blockIdx.y * 128;
    const int bn  = blockIdx.x * 128;

    float* C = (out_sel == 0) ? g_Q : (out_sel == 1) ? g_K : g_V;

    // load row pointers
    const int am = bm + (tid >> 1);
    const float* arow;
    if (mode == 1) {
        const int b = am / SEQ_S;
        const int s = am % SEQ_S;
        arow = (s < LEN) ? (A1 + ((size_t)b * LEN + s) * D_EMBED)
                         : (A2 + ((size_t)b * 2 * LEN + (s - LEN)) * D_EMBED);
    } else if (mode == 2) {
        arow = g_CTX + (size_t)am * D_EMBED;
    } else {
        arow = A1 + (size_t)am * D_EMBED;
    }
    const float* brow = W + (size_t)(bn + (tid >> 1)) * D_EMBED;
    const int koff = (tid & 1) * 4;
    const int srow = tid >> 1;

    const int ra = (tid >> 4) * 4;   // rows ra..ra+3 and 64+ra..64+ra+3
    const int ca = (tid & 15) * 4;   // cols ca..ca+3 and 64+ca..64+ca+3

    float acc[8][8];
    #pragma unroll
    for (int i = 0; i < 8; i++)
        #pragma unroll
        for (int j = 0; j < 8; j++) acc[i][j] = 0.f;

    float4 pa = *(const float4*)(arow + koff);
    float4 pb = *(const float4*)(brow + koff);

    for (int k0 = 0; k0 < D_EMBED; k0 += 8) {
        As[koff + 0][srow] = pa.x; As[koff + 1][srow] = pa.y;
        As[koff + 2][srow] = pa.z; As[koff + 3][srow] = pa.w;
        Bs[koff + 0][srow] = pb.x; Bs[koff + 1][srow] = pb.y;
        Bs[koff + 2][srow] = pb.z; Bs[koff + 3][srow] = pb.w;
        __syncthreads();

        if (k0 + 8 < D_EMBED) {
            pa = *(const float4*)(arow + k0 + 8 + koff);
            pb = *(const float4*)(brow + k0 + 8 + koff);
        }

        #pragma unroll
        for (int kk = 0; kk < 8; kk++) {
            float a[8], b[8];
            *(float4*)&a[0] = *(const float4*)&As[kk][ra];
            *(float4*)&a[4] = *(const float4*)&As[kk][64 + ra];
            *(float4*)&b[0] = *(const float4*)&Bs[kk][ca];
            *(float4*)&b[4] = *(const float4*)&Bs[kk][64 + ca];
            #pragma unroll
            for (int i = 0; i < 8; i++)
                #pragma unroll
                for (int j = 0; j < 8; j++)
                    acc[i][j] += a[i] * b[j];
        }
        __syncthreads();
    }

    const float4 bia = *(const float4*)(bias + bn + ca);
    const float4 bib = *(const float4*)(bias + bn + 64 + ca);

    #pragma unroll
    for (int i = 0; i < 8; i++) {
        const int row = bm + ((i < 4) ? (ra + i) : (64 + ra + i - 4));
        float* crow = C + (size_t)row * D_EMBED + bn;
        float4 o;
        o.x = acc[i][0] + bia.x; o.y = acc[i][1] + bia.y;
        o.z = acc[i][2] + bia.z; o.w = acc[i][3] + bia.w;
        *(float4*)(crow + ca) = o;
        o.x = acc[i][4] + bib.x; o.y = acc[i][5] + bib.y;
        o.z = acc[i][6] + bib.z; o.w = acc[i][7] + bib.w;
        *(float4*)(crow + 64 + ca) = o;
    }
}

// ---------------------------------------------------------------------------
// Flash attention: per block (qt, b*H+h): 64 queries x dh=64 over S=3072 keys,
// tripled causal mask (per 1024-segment, key_local > query_local masked).
// Fully masked key tiles skipped (kt <= qt only).
// smem: Qt,Kt k-major stride 65; Vs row-major stride 68; Ps [q][key] stride 65.
// ---------------------------------------------------------------------------
#define ATTN_SMEM_FLOATS (64*65 + 64*65 + 64*68 + 64*65)
#define ATTN_SMEM_BYTES  (ATTN_SMEM_FLOATS * 4)

__global__ void __launch_bounds__(256) attn_kernel()
{
    extern __shared__ float sm[];
    float* Qt = sm;                    // [d][tok] stride 65
    float* Kt = Qt + 64 * 65;          // [d][tok] stride 65
    float* Vs = Kt + 64 * 65;          // [tok][d] stride 68
    float* Ps = Vs + 64 * 68;          // [q][key] stride 65

    const int tid = threadIdx.x;
    const int qt  = blockIdx.x;        // 0..15
    const int b   = blockIdx.y >> 4;
    const int h   = blockIdx.y & 15;
    const int q0  = qt * 64;

    // load Q tile transposed to k-major
    {
        const float* Qbase = g_Q + ((size_t)(b * LEN + q0)) * D_EMBED + h * DH;
        #pragma unroll
        for (int rep = 0; rep < 4; rep++) {
            const int li  = tid + rep * 256;
            const int tok = li >> 4;
            const int d4  = (li & 15) << 2;
            float4 v = *(const float4*)(Qbase + (size_t)tok * D_EMBED + d4);
            Qt[(d4 + 0) * 65 + tok] = v.x;
            Qt[(d4 + 1) * 65 + tok] = v.y;
            Qt[(d4 + 2) * 65 + tok] = v.z;
            Qt[(d4 + 3) * 65 + tok] = v.w;
        }
    }

    float acc[16];
    #pragma unroll
    for (int i = 0; i < 16; i++) acc[i] = 0.f;
    float m_run = -1e30f, l_run = 0.f;

    const int r   = tid >> 2;          // query row for softmax/PV
    const int qi  = tid & 3;           // 16-wide dh quarter
    const int str = (tid >> 4) * 4;    // S-compute 4x4 tile coords
    const int stc = (tid & 15) * 4;

    for (int seg = 0; seg < 3; seg++) {
        const float* Kbase = g_K + ((size_t)(b * SEQ_S + seg * LEN)) * D_EMBED + h * DH;
        const float* Vbase = g_V + ((size_t)(b * SEQ_S + seg * LEN)) * D_EMBED + h * DH;
        for (int kt = 0; kt <= qt; kt++) {
            const int s0 = kt * 64;
            __syncthreads();           // prev iteration consumers done
            #pragma unroll
            for (int rep = 0; rep < 4; rep++) {
                const int li  = tid + rep * 256;
                const int tok = li >> 4;
                const int d4  = (li & 15) << 2;
                float4 kv = *(const float4*)(Kbase + (size_t)(s0 + tok) * D_EMBED + d4);
                Kt[(d4 + 0) * 65 + tok] = kv.x;
                Kt[(d4 + 1) * 65 + tok] = kv.y;
                Kt[(d4 + 2) * 65 + tok] = kv.z;
                Kt[(d4 + 3) * 65 + tok] = kv.w;
                float4 vv = *(const float4*)(Vbase + (size_t)(s0 + tok) * D_EMBED + d4);
                *(float4*)&Vs[tok * 68 + d4] = vv;
            }
            __syncthreads();

            // S tile = Q K^T * 0.125, with diagonal-tile causal mask
            {
                float s4[4][4];
                #pragma unroll
                for (int i = 0; i < 4; i++)
                    #pragma unroll
                    for (int j = 0; j < 4; j++) s4[i][j] = 0.f;

                #pragma unroll 8
                for (int k = 0; k < 64; k++) {
                    const float* qr = Qt + k * 65;
                    const float* kr = Kt + k * 65;
                    const float a0 = qr[str + 0], a1 = qr[str + 1];
                    const float a2 = qr[str + 2], a3 = qr[str + 3];
                    const float b0 = kr[stc + 0], b1 = kr[stc + 1];
                    const float b2 = kr[stc + 2], b3 = kr[stc + 3];
                    s4[0][0] += a0 * b0; s4[0][1] += a0 * b1; s4[0][2] += a0 * b2; s4[0][3] += a0 * b3;
                    s4[1][0] += a1 * b0; s4[1][1] += a1 * b1; s4[1][2] += a1 * b2; s4[1][3] += a1 * b3;
                    s4[2][0] += a2 * b0; s4[2][1] += a2 * b1; s4[2][2] += a2 * b2; s4[2][3] += a2 * b3;
                    s4[3][0] += a3 * b0; s4[3][1] += a3 * b1; s4[3][2] += a3 * b2; s4[3][3] += a3 * b3;
                }
                const bool diag = (kt == qt);
                #pragma unroll
                for (int i = 0; i < 4; i++)
                    #pragma unroll
                    for (int j = 0; j < 4; j++) {
                        float val = s4[i][j] * 0.125f;
                        if (diag && (stc + j) > (str + i)) val = -1e30f;
                        Ps[(str + i) * 65 + (stc + j)] = val;
                    }
            }
            __syncthreads();

            // online softmax + PV
            {
                const float* prow = Ps + r * 65;
                float tmax = -1e30f;
                #pragma unroll 16
                for (int c = 0; c < 64; c++) tmax = fmaxf(tmax, prow[c]);
                const float new_m = fmaxf(m_run, tmax);
                const float alpha = __expf(m_run - new_m);
                #pragma unroll
                for (int i = 0; i < 16; i++) acc[i] *= alpha;
                float lsum = 0.f;
                #pragma unroll 8
                for (int c = 0; c < 64; c++) {
                    const float p = __expf(prow[c] - new_m);
                    lsum += p;
                    const float* vr = Vs + c * 68 + qi * 16;
                    const float4 v0 = *(const float4*)(vr + 0);
                    const float4 v1 = *(const float4*)(vr + 4);
                    const float4 v2 = *(const float4*)(vr + 8);
                    const float4 v3 = *(const float4*)(vr + 12);
                    acc[0]  += p * v0.x; acc[1]  += p * v0.y; acc[2]  += p * v0.z; acc[3]  += p * v0.w;
                    acc[4]  += p * v1.x; acc[5]  += p * v1.y; acc[6]  += p * v1.z; acc[7]  += p * v1.w;
                    acc[8]  += p * v2.x; acc[9]  += p * v2.y; acc[10] += p * v2.z; acc[11] += p * v2.w;
                    acc[12] += p * v3.x; acc[13] += p * v3.y; acc[14] += p * v3.z; acc[15] += p * v3.w;
                }
                l_run = l_run * alpha + lsum;
                m_run = new_m;
            }
        }
    }

    const float inv = 1.f / l_run;
    float* out = g_CTX + ((size_t)(b * LEN + q0 + r)) * D_EMBED + h * DH + qi * 16;
    #pragma unroll
    for (int i = 0; i < 16; i += 4) {
        float4 o;
        o.x = acc[i + 0] * inv; o.y = acc[i + 1] * inv;
        o.z = acc[i + 2] * inv; o.w = acc[i + 3] * inv;
        *(float4*)(out + i) = o;
    }
}

// ---------------------------------------------------------------------------
// Residual + LayerNorm + mask epilogue. One block per row (1024 elems, 256 thr).
// attn_out lives in g_K (reused after attention consumed K).
// ---------------------------------------------------------------------------
__global__ void __launch_bounds__(256) ln_mask_kernel(
    const float* __restrict__ hq, const float* __restrict__ lng,
    const float* __restrict__ lnb, const float* __restrict__ mask,
    float* __restrict__ out)
{
    __shared__ float red[32];
    const int row = blockIdx.x;
    const int tid = threadIdx.x;

    const float4 a = *(const float4*)(hq  + (size_t)row * D_EMBED + tid * 4);
    const float4 c = *(const float4*)(g_K + (size_t)row * D_EMBED + tid * 4);
    const float x0 = a.x + c.x, x1 = a.y + c.y, x2 = a.z + c.z, x3 = a.w + c.w;

    float s  = x0 + x1 + x2 + x3;
    float ss = x0 * x0 + x1 * x1 + x2 * x2 + x3 * x3;
    #pragma unroll
    for (int o = 16; o > 0; o >>= 1) {
        s  += __shfl_xor_sync(0xFFFFFFFFu, s,  o);
        ss += __shfl_xor_sync(0xFFFFFFFFu, ss, o);
    }
    const int w = tid >> 5;
    if ((tid & 31) == 0) { red[w] = s; red[w + 8] = ss; }
    __syncthreads();
    if (tid < 32) {
        float s2  = (tid < 8) ? red[tid]     : 0.f;
        float ss2 = (tid < 8) ? red[tid + 8] : 0.f;
        #pragma unroll
        for (int o = 4; o > 0; o >>= 1) {
            s2  += __shfl_xor_sync(0xFFFFFFFFu, s2,  o);
            ss2 += __shfl_xor_sync(0xFFFFFFFFu, ss2, o);
        }
        if (tid == 0) { red[16] = s2; red[17] = ss2; }
    }
    __syncthreads();

    const float mu   = red[16] * (1.f / 1024.f);
    const float var  = red[17] * (1.f / 1024.f) - mu * mu;
    const float rstd = rsqrtf(var + 1e-5f);
    const float mk   = mask[row];

    const float4 g = *(const float4*)(lng + tid * 4);
    const float4 b = *(const float4*)(lnb + tid * 4);
    float4 o;
    o.x = ((x0 - mu) * rstd * g.x + b.x) * mk;
    o.y = ((x1 - mu) * rstd * g.y + b.y) * mk;
    o.z = ((x2 - mu) * rstd * g.z + b.z) * mk;
    o.w = ((x3 - mu) * rstd * g.w + b.w) * mk;
    *(float4*)(out + (size_t)row * D_EMBED + tid * 4) = o;
}

// ---------------------------------------------------------------------------
extern "C" void kernel_launch(void* const* d_in, const int* in_sizes, int n_in,
                              void* d_out, int out_size)
{
    const float* h_q   = (const float*)d_in[0];
    const float* h_kv1 = (const float*)d_in[1];
    const float* h_kv2 = (const float*)d_in[2];
    const float* mask  = (const float*)d_in[3];
    const float* w_in  = (const float*)d_in[4];
    const float* b_in  = (const float*)d_in[5];
    const float* w_out = (const float*)d_in[6];
    const float* b_out = (const float*)d_in[7];
    const float* ln_g  = (const float*)d_in[8];
    const float* ln_b  = (const float*)d_in[9];
    float* out = (float*)d_out;

    cudaFuncSetAttribute(attn_kernel,
                         cudaFuncAttributeMaxDynamicSharedMemorySize,
                         ATTN_SMEM_BYTES);

    const dim3 gq(8, 16);   // N=1024/128, M=2048/128
    const dim3 gk(8, 48);   // M=6144/128

    // Q = h_q @ Wq^T + bq
    sgemm_nt<<<gq, 256>>>(h_q, nullptr, 0, w_in, b_in, 0, BATCH * LEN);
    // K = concat(h_kv1,h_kv2) @ Wk^T + bk
    sgemm_nt<<<gk, 256>>>(h_kv1, h_kv2, 1, w_in + 1 * D_EMBED * D_EMBED,
                          b_in + 1 * D_EMBED, 1, BATCH * SEQ_S);
    // V
    sgemm_nt<<<gk, 256>>>(h_kv1, h_kv2, 1, w_in + 2 * D_EMBED * D_EMBED,
                          b_in + 2 * D_EMBED, 2, BATCH * SEQ_S);
    // attention -> g_CTX
    attn_kernel<<<dim3(16, BATCH * N_HEAD), 256, ATTN_SMEM_BYTES>>>();
    // attn_out = ctx @ out_w^T + out_b   (into g_K, now free)
    sgemm_nt<<<gq, 256>>>(nullptr, nullptr, 2, w_out, b_out, 1, BATCH * LEN);
    // residual + LN + mask
    ln_mask_kernel<<<BATCH * LEN, 256>>>(h_q, ln_g, ln_b, mask, out);
}

// round 6
// speedup vs baseline: 1.2140x; 1.2140x over previous
#include <cuda_runtime.h>
#include <cuda_bf16.h>
#include <cstdint>

// Problem constants
#define D_EMBED 1024
#define N_HEAD  16
#define DH      64
#define LEN     1024
#define SEQ_S   3072
#define BATCH   2

// Scratch (device globals: allocation-free)
__device__ float g_Q  [BATCH * LEN   * D_EMBED];   // 8 MB
__device__ float g_K  [BATCH * SEQ_S * D_EMBED];   // 24 MB (reused for attn_out)
__device__ float g_V  [BATCH * SEQ_S * D_EMBED];   // 24 MB
__device__ float g_CTX[BATCH * LEN   * D_EMBED];   // 8 MB

// ---------------------------------------------------------------------------
// tf32 helpers (baseline sm_80+ PTX only)
// ---------------------------------------------------------------------------
__device__ __forceinline__ uint32_t f2tf(float f) {
    uint32_t r;
    asm("cvt.rna.tf32.f32 %0, %1;" : "=r"(r) : "f"(f));
    return r;
}
__device__ __forceinline__ void mma_tf32(float* d, uint32_t a0, uint32_t a1,
                                         uint32_t a2, uint32_t a3,
                                         uint32_t b0, uint32_t b1) {
    asm volatile("mma.sync.aligned.m16n8k8.row.col.f32.tf32.tf32.f32 "
                 "{%0,%1,%2,%3}, {%4,%5,%6,%7}, {%8,%9}, {%0,%1,%2,%3};"
                 : "+f"(d[0]), "+f"(d[1]), "+f"(d[2]), "+f"(d[3])
                 : "r"(a0), "r"(a1), "r"(a2), "r"(a3), "r"(b0), "r"(b1));
}

// ---------------------------------------------------------------------------
// tf32 tensor-core GEMM:  C[m,n] = sum_k A[m,k]*W[n,k] + bias[n]
// A row-major (M x 1024), W row-major (N x 1024), fp32 out.
// CTA tile 128x128, BK=32, 256 thr = 8 warps (4m x 2n, each 32x64).
// Fragments loaded with plain LDS per the PTX ISA m16n8k8 tf32 tables:
//   A: a0(r=g, c=t) a1(r=g+8, c=t) a2(r=g, c=t+4) a3(r=g+8, c=t+4)
//   B: b0(k=t, n=g) b1(k=t+4, n=g)          [g=lane/4, t=lane%4]
//   D: c0(r=g, c=2t) c1(c=2t+1) c2(r=g+8) c3
// smem stride 36 u32 -> fragment LDS bank = (4g+t) mod 32, conflict-free.
// mode: 0 = A1 contiguous rows; 1 = KV concat gather; 2 = read g_CTX
// out_sel: 0 = g_Q, 1 = g_K, 2 = g_V
// ---------------------------------------------------------------------------
#define GS 36   // smem row stride in u32

__global__ void __launch_bounds__(256) gemm_tf32(
    const float* __restrict__ A1, const float* __restrict__ A2, int mode,
    const float* __restrict__ W,  const float* __restrict__ bias, int out_sel)
{
    __shared__ uint32_t sA[128 * GS];
    __shared__ uint32_t sB[128 * GS];

    const int tid = threadIdx.x;
    const int wid = tid >> 5;
    const int lan = tid & 31;
    const int bm  = blockIdx.y * 128;
    const int bn  = blockIdx.x * 128;

    float* C = (out_sel == 0) ? g_Q : (out_sel == 1) ? g_K : g_V;

    const int mw = wid & 3;              // row block: mw*32
    const int nw = wid >> 2;             // col block: nw*64
    const int g  = lan >> 2;             // groupID
    const int tg = lan & 3;              // threadID_in_group

    // ---- per-thread load geometry: row = tid>>1, 16 cols at lc ----
    const int lr = tid >> 1;
    const int lc = (tid & 1) * 16;

    const float* arow;
    {
        const int am = bm + lr;
        if (mode == 1) {
            const int b = am / SEQ_S;
            const int s = am % SEQ_S;
            arow = (s < LEN) ? (A1 + ((size_t)b * LEN + s) * D_EMBED)
                             : (A2 + ((size_t)b * 2 * LEN + (s - LEN)) * D_EMBED);
        } else if (mode == 2) {
            arow = g_CTX + (size_t)(bm + lr) * D_EMBED;
        } else {
            arow = A1 + (size_t)(bm + lr) * D_EMBED;
        }
    }
    const float* brow = W + (size_t)(bn + lr) * D_EMBED;

    float acc[2][8][4];
    #pragma unroll
    for (int mt = 0; mt < 2; mt++)
        #pragma unroll
        for (int nt = 0; nt < 8; nt++)
            #pragma unroll
            for (int e = 0; e < 4; e++) acc[mt][nt][e] = 0.f;

    // fragment base indices (u32 offsets into sA/sB)
    const int aBase = (mw * 32 + g) * GS + tg;      // + mt*16*GS + 8*GS(row+8) + ks*8 (+4)
    const int bBase = (nw * 64 + g) * GS + tg;      // + nt*8*GS + ks*8 (+4)

    // ---- prefetch tile 0 into registers ----
    float4 fa[4], fb[4];
    #pragma unroll
    for (int j = 0; j < 4; j++) {
        fa[j] = *(const float4*)(arow + lc + 4 * j);
        fb[j] = *(const float4*)(brow + lc + 4 * j);
    }

    for (int it = 0; it < 32; it++) {
        __syncthreads();                 // previous compute done -> smem free

        #pragma unroll
        for (int j = 0; j < 4; j++) {
            uint4 ua = make_uint4(f2tf(fa[j].x), f2tf(fa[j].y),
                                  f2tf(fa[j].z), f2tf(fa[j].w));
            uint4 ub = make_uint4(f2tf(fb[j].x), f2tf(fb[j].y),
                                  f2tf(fb[j].z), f2tf(fb[j].w));
            *(uint4*)&sA[lr * GS + lc + 4 * j] = ua;
            *(uint4*)&sB[lr * GS + lc + 4 * j] = ub;
        }
        __syncthreads();

        // prefetch next tile (overlaps compute below)
        if (it + 1 < 32) {
            const int kg = (it + 1) * 32;
            #pragma unroll
            for (int j = 0; j < 4; j++) {
                fa[j] = *(const float4*)(arow + kg + lc + 4 * j);
                fb[j] = *(const float4*)(brow + kg + lc + 4 * j);
            }
        }

        // compute: 4 k-steps of 8
        #pragma unroll
        for (int ks = 0; ks < 4; ks++) {
            const int ko = ks * 8;
            uint32_t af[2][4];
            #pragma unroll
            for (int mt = 0; mt < 2; mt++) {
                const int ab = aBase + mt * 16 * GS + ko;
                af[mt][0] = sA[ab];
                af[mt][1] = sA[ab + 8 * GS];
                af[mt][2] = sA[ab + 4];
                af[mt][3] = sA[ab + 8 * GS + 4];
            }
            uint32_t bf[8][2];
            #pragma unroll
            for (int nt = 0; nt < 8; nt++) {
                const int bb = bBase + nt * 8 * GS + ko;
                bf[nt][0] = sB[bb];
                bf[nt][1] = sB[bb + 4];
            }
            #pragma unroll
            for (int mt = 0; mt < 2; mt++)
                #pragma unroll
                for (int nt = 0; nt < 8; nt++)
                    mma_tf32(acc[mt][nt], af[mt][0], af[mt][1], af[mt][2],
                             af[mt][3], bf[nt][0], bf[nt][1]);
        }
    }

    // ---- epilogue (PTX ISA D-fragment layout) ----
    const int erow = g;
    const int ecol = tg * 2;
    #pragma unroll
    for (int mt = 0; mt < 2; mt++) {
        const int row = bm + mw * 32 + mt * 16 + erow;
        #pragma unroll
        for (int nt = 0; nt < 8; nt++) {
            const int col = bn + nw * 64 + nt * 8 + ecol;
            const float c0 = __ldg(bias + col), c1 = __ldg(bias + col + 1);
            float2 lo, hi;
            lo.x = acc[mt][nt][0] + c0; lo.y = acc[mt][nt][1] + c1;
            hi.x = acc[mt][nt][2] + c0; hi.y = acc[mt][nt][3] + c1;
            *(float2*)(C + (size_t)row * 1024 + col)       = lo;
            *(float2*)(C + (size_t)(row + 8) * 1024 + col) = hi;
        }
    }
}

// ---------------------------------------------------------------------------
// Flash attention (fp32) — VERBATIM R1 (proven, rel_err 7.5e-8)
// ---------------------------------------------------------------------------
#define ATTN_SMEM_FLOATS (64*65 + 64*65 + 64*68 + 64*65)
#define ATTN_SMEM_BYTES  (ATTN_SMEM_FLOATS * 4)

__global__ void __launch_bounds__(256) attn_kernel()
{
    extern __shared__ float smf[];
    float* Qt = smf;                   // [d][tok] stride 65
    float* Kt = Qt + 64 * 65;
    float* Vs = Kt + 64 * 65;          // [tok][d] stride 68
    float* Ps = Vs + 64 * 68;          // [q][key] stride 65

    const int tid = threadIdx.x;
    const int qt  = blockIdx.x;        // 0..15
    const int b   = blockIdx.y >> 4;
    const int h   = blockIdx.y & 15;
    const int q0  = qt * 64;

    {
        const float* Qbase = g_Q + ((size_t)(b * LEN + q0)) * D_EMBED + h * DH;
        #pragma unroll
        for (int rep = 0; rep < 4; rep++) {
            const int li  = tid + rep * 256;
            const int tok = li >> 4;
            const int d4  = (li & 15) << 2;
            float4 v = *(const float4*)(Qbase + (size_t)tok * D_EMBED + d4);
            Qt[(d4 + 0) * 65 + tok] = v.x;
            Qt[(d4 + 1) * 65 + tok] = v.y;
            Qt[(d4 + 2) * 65 + tok] = v.z;
            Qt[(d4 + 3) * 65 + tok] = v.w;
        }
    }

    float acc[16];
    #pragma unroll
    for (int i = 0; i < 16; i++) acc[i] = 0.f;
    float m_run = -1e30f, l_run = 0.f;

    const int r   = tid >> 2;
    const int qi  = tid & 3;
    const int str = (tid >> 4) * 4;
    const int stc = (tid & 15) * 4;

    for (int seg = 0; seg < 3; seg++) {
        const float* Kbase = g_K + ((size_t)(b * SEQ_S + seg * LEN)) * D_EMBED + h * DH;
        const float* Vbase = g_V + ((size_t)(b * SEQ_S + seg * LEN)) * D_EMBED + h * DH;
        for (int kt = 0; kt <= qt; kt++) {
            const int s0 = kt * 64;
            __syncthreads();
            #pragma unroll
            for (int rep = 0; rep < 4; rep++) {
                const int li  = tid + rep * 256;
                const int tok = li >> 4;
                const int d4  = (li & 15) << 2;
                float4 kv = *(const float4*)(Kbase + (size_t)(s0 + tok) * D_EMBED + d4);
                Kt[(d4 + 0) * 65 + tok] = kv.x;
                Kt[(d4 + 1) * 65 + tok] = kv.y;
                Kt[(d4 + 2) * 65 + tok] = kv.z;
                Kt[(d4 + 3) * 65 + tok] = kv.w;
                float4 vv = *(const float4*)(Vbase + (size_t)(s0 + tok) * D_EMBED + d4);
                *(float4*)&Vs[tok * 68 + d4] = vv;
            }
            __syncthreads();

            {
                float s4[4][4];
                #pragma unroll
                for (int i = 0; i < 4; i++)
                    #pragma unroll
                    for (int j = 0; j < 4; j++) s4[i][j] = 0.f;

                #pragma unroll 8
                for (int k = 0; k < 64; k++) {
                    const float* qr = Qt + k * 65;
                    const float* kr = Kt + k * 65;
                    const float a0 = qr[str + 0], a1 = qr[str + 1];
                    const float a2 = qr[str + 2], a3 = qr[str + 3];
                    const float b0 = kr[stc + 0], b1 = kr[stc + 1];
                    const float b2 = kr[stc + 2], b3 = kr[stc + 3];
                    s4[0][0] += a0 * b0; s4[0][1] += a0 * b1; s4[0][2] += a0 * b2; s4[0][3] += a0 * b3;
                    s4[1][0] += a1 * b0; s4[1][1] += a1 * b1; s4[1][2] += a1 * b2; s4[1][3] += a1 * b3;
                    s4[2][0] += a2 * b0; s4[2][1] += a2 * b1; s4[2][2] += a2 * b2; s4[2][3] += a2 * b3;
                    s4[3][0] += a3 * b0; s4[3][1] += a3 * b1; s4[3][2] += a3 * b2; s4[3][3] += a3 * b3;
                }
                const bool diag = (kt == qt);
                #pragma unroll
                for (int i = 0; i < 4; i++)
                    #pragma unroll
                    for (int j = 0; j < 4; j++) {
                        float val = s4[i][j] * 0.125f;
                        if (diag && (stc + j) > (str + i)) val = -1e30f;
                        Ps[(str + i) * 65 + (stc + j)] = val;
                    }
            }
            __syncthreads();

            {
                const float* prow = Ps + r * 65;
                float tmax = -1e30f;
                #pragma unroll 16
                for (int c = 0; c < 64; c++) tmax = fmaxf(tmax, prow[c]);
                const float new_m = fmaxf(m_run, tmax);
                const float alpha = __expf(m_run - new_m);
                #pragma unroll
                for (int i = 0; i < 16; i++) acc[i] *= alpha;
                float lsum = 0.f;
                #pragma unroll 8
                for (int c = 0; c < 64; c++) {
                    const float p = __expf(prow[c] - new_m);
                    lsum += p;
                    const float* vr = Vs + c * 68 + qi * 16;
                    const float4 v0 = *(const float4*)(vr + 0);
                    const float4 v1 = *(const float4*)(vr + 4);
                    const float4 v2 = *(const float4*)(vr + 8);
                    const float4 v3 = *(const float4*)(vr + 12);
                    acc[0]  += p * v0.x; acc[1]  += p * v0.y; acc[2]  += p * v0.z; acc[3]  += p * v0.w;
                    acc[4]  += p * v1.x; acc[5]  += p * v1.y; acc[6]  += p * v1.z; acc[7]  += p * v1.w;
                    acc[8]  += p * v2.x; acc[9]  += p * v2.y; acc[10] += p * v2.z; acc[11] += p * v2.w;
                    acc[12] += p * v3.x; acc[13] += p * v3.y; acc[14] += p * v3.z; acc[15] += p * v3.w;
                }
                l_run = l_run * alpha + lsum;
                m_run = new_m;
            }
        }
    }

    const float inv = 1.f / l_run;
    float* out = g_CTX + ((size_t)(b * LEN + q0 + r)) * D_EMBED + h * DH + qi * 16;
    #pragma unroll
    for (int i = 0; i < 16; i += 4) {
        float4 o;
        o.x = acc[i + 0] * inv; o.y = acc[i + 1] * inv;
        o.z = acc[i + 2] * inv; o.w = acc[i + 3] * inv;
        *(float4*)(out + i) = o;
    }
}

// ---------------------------------------------------------------------------
// Residual + LayerNorm + mask epilogue — VERBATIM R1
// ---------------------------------------------------------------------------
__global__ void __launch_bounds__(256) ln_mask_kernel(
    const float* __restrict__ hq, const float* __restrict__ lng,
    const float* __restrict__ lnb, const float* __restrict__ mask,
    float* __restrict__ out)
{
    __shared__ float red[32];
    const int row = blockIdx.x;
    const int tid = threadIdx.x;

    const float4 a = *(const float4*)(hq  + (size_t)row * D_EMBED + tid * 4);
    const float4 c = *(const float4*)(g_K + (size_t)row * D_EMBED + tid * 4);
    const float x0 = a.x + c.x, x1 = a.y + c.y, x2 = a.z + c.z, x3 = a.w + c.w;

    float s  = x0 + x1 + x2 + x3;
    float ss = x0 * x0 + x1 * x1 + x2 * x2 + x3 * x3;
    #pragma unroll
    for (int o = 16; o > 0; o >>= 1) {
        s  += __shfl_xor_sync(0xFFFFFFFFu, s,  o);
        ss += __shfl_xor_sync(0xFFFFFFFFu, ss, o);
    }
    const int w = tid >> 5;
    if ((tid & 31) == 0) { red[w] = s; red[w + 8] = ss; }
    __syncthreads();
    if (tid < 32) {
        float s2  = (tid < 8) ? red[tid]     : 0.f;
        float ss2 = (tid < 8) ? red[tid + 8] : 0.f;
        #pragma unroll
        for (int o = 4; o > 0; o >>= 1) {
            s2  += __shfl_xor_sync(0xFFFFFFFFu, s2,  o);
            ss2 += __shfl_xor_sync(0xFFFFFFFFu, ss2, o);
        }
        if (tid == 0) { red[16] = s2; red[17] = ss2; }
    }
    __syncthreads();

    const float mu   = red[16] * (1.f / 1024.f);
    const float var  = red[17] * (1.f / 1024.f) - mu * mu;
    const float rstd = rsqrtf(var + 1e-5f);
    const float mk   = mask[row];

    const float4 gg = *(const float4*)(lng + tid * 4);
    const float4 bb = *(const float4*)(lnb + tid * 4);
    float4 o;
    o.x = ((x0 - mu) * rstd * gg.x + bb.x) * mk;
    o.y = ((x1 - mu) * rstd * gg.y + bb.y) * mk;
    o.z = ((x2 - mu) * rstd * gg.z + bb.z) * mk;
    o.w = ((x3 - mu) * rstd * gg.w + bb.w) * mk;
    *(float4*)(out + (size_t)row * D_EMBED + tid * 4) = o;
}

// ---------------------------------------------------------------------------
extern "C" void kernel_launch(void* const* d_in, const int* in_sizes, int n_in,
                              void* d_out, int out_size)
{
    const float* h_q   = (const float*)d_in[0];
    const float* h_kv1 = (const float*)d_in[1];
    const float* h_kv2 = (const float*)d_in[2];
    const float* mask  = (const float*)d_in[3];
    const float* w_in  = (const float*)d_in[4];
    const float* b_in  = (const float*)d_in[5];
    const float* w_out = (const float*)d_in[6];
    const float* b_out = (const float*)d_in[7];
    const float* ln_g  = (const float*)d_in[8];
    const float* ln_b  = (const float*)d_in[9];
    float* out = (float*)d_out;

    cudaFuncSetAttribute(attn_kernel,
                         cudaFuncAttributeMaxDynamicSharedMemorySize,
                         ATTN_SMEM_BYTES);

    const dim3 gq(8, 16);   // N=1024/128, M=2048/128
    const dim3 gk(8, 48);   // M=6144/128

    // Q = h_q @ Wq^T + bq
    gemm_tf32<<<gq, 256>>>(h_q, nullptr, 0, w_in, b_in, 0);
    // K = concat(h_kv1,h_kv2) @ Wk^T + bk
    gemm_tf32<<<gk, 256>>>(h_kv1, h_kv2, 1, w_in + (size_t)1024 * 1024,
                           b_in + 1024, 1);
    // V
    gemm_tf32<<<gk, 256>>>(h_kv1, h_kv2, 1, w_in + (size_t)2048 * 1024,
                           b_in + 2048, 2);
    // attention -> g_CTX
    attn_kernel<<<dim3(16, BATCH * N_HEAD), 256, ATTN_SMEM_BYTES>>>();
    // attn_out = ctx @ out_w^T + out_b  (into g_K, now free)
    gemm_tf32<<<gq, 256>>>(nullptr, nullptr, 2, w_out, b_out, 1);
    // residual + LN + mask
    ln_mask_kernel<<<BATCH * LEN, 256>>>(h_q, ln_g, ln_b, mask, out);
}

// round 7
// speedup vs baseline: 3.5745x; 2.9445x over previous
#include <cuda_runtime.h>
#include <cuda_bf16.h>
#include <cstdint>

// Problem constants
#define D_EMBED 1024
#define N_HEAD  16
#define DH      64
#define LEN     1024
#define SEQ_S   3072
#define BATCH   2

// Scratch (device globals: allocation-free)
__device__ float g_Q  [BATCH * LEN   * D_EMBED];   // 8 MB
__device__ float g_K  [BATCH * SEQ_S * D_EMBED];   // 24 MB (reused for attn_out)
__device__ float g_V  [BATCH * SEQ_S * D_EMBED];   // 24 MB
__device__ float g_CTX[BATCH * LEN   * D_EMBED];   // 8 MB

// ---------------------------------------------------------------------------
// tf32 helpers (baseline sm_80+ PTX only)
// ---------------------------------------------------------------------------
__device__ __forceinline__ uint32_t f2tf(float f) {
    uint32_t r;
    asm("cvt.rna.tf32.f32 %0, %1;" : "=r"(r) : "f"(f));
    return r;
}
__device__ __forceinline__ void mma_tf32(float* d, uint32_t a0, uint32_t a1,
                                         uint32_t a2, uint32_t a3,
                                         uint32_t b0, uint32_t b1) {
    asm volatile("mma.sync.aligned.m16n8k8.row.col.f32.tf32.tf32.f32 "
                 "{%0,%1,%2,%3}, {%4,%5,%6,%7}, {%8,%9}, {%0,%1,%2,%3};"
                 : "+f"(d[0]), "+f"(d[1]), "+f"(d[2]), "+f"(d[3])
                 : "r"(a0), "r"(a1), "r"(a2), "r"(a3), "r"(b0), "r"(b1));
}

// ---------------------------------------------------------------------------
// tf32 tensor-core GEMM — VERBATIM R6 (proven)
// ---------------------------------------------------------------------------
#define GS 36   // smem row stride in u32

__global__ void __launch_bounds__(256) gemm_tf32(
    const float* __restrict__ A1, const float* __restrict__ A2, int mode,
    const float* __restrict__ W,  const float* __restrict__ bias, int out_sel)
{
    __shared__ uint32_t sA[128 * GS];
    __shared__ uint32_t sB[128 * GS];

    const int tid = threadIdx.x;
    const int wid = tid >> 5;
    const int lan = tid & 31;
    const int bm  = blockIdx.y * 128;
    const int bn  = blockIdx.x * 128;

    float* C = (out_sel == 0) ? g_Q : (out_sel == 1) ? g_K : g_V;

    const int mw = wid & 3;
    const int nw = wid >> 2;
    const int g  = lan >> 2;
    const int tg = lan & 3;

    const int lr = tid >> 1;
    const int lc = (tid & 1) * 16;

    const float* arow;
    {
        const int am = bm + lr;
        if (mode == 1) {
            const int b = am / SEQ_S;
            const int s = am % SEQ_S;
            arow = (s < LEN) ? (A1 + ((size_t)b * LEN + s) * D_EMBED)
                             : (A2 + ((size_t)b * 2 * LEN + (s - LEN)) * D_EMBED);
        } else if (mode == 2) {
            arow = g_CTX + (size_t)(bm + lr) * D_EMBED;
        } else {
            arow = A1 + (size_t)(bm + lr) * D_EMBED;
        }
    }
    const float* brow = W + (size_t)(bn + lr) * D_EMBED;

    float acc[2][8][4];
    #pragma unroll
    for (int mt = 0; mt < 2; mt++)
        #pragma unroll
        for (int nt = 0; nt < 8; nt++)
            #pragma unroll
            for (int e = 0; e < 4; e++) acc[mt][nt][e] = 0.f;

    const int aBase = (mw * 32 + g) * GS + tg;
    const int bBase = (nw * 64 + g) * GS + tg;

    float4 fa[4], fb[4];
    #pragma unroll
    for (int j = 0; j < 4; j++) {
        fa[j] = *(const float4*)(arow + lc + 4 * j);
        fb[j] = *(const float4*)(brow + lc + 4 * j);
    }

    for (int it = 0; it < 32; it++) {
        __syncthreads();

        #pragma unroll
        for (int j = 0; j < 4; j++) {
            uint4 ua = make_uint4(f2tf(fa[j].x), f2tf(fa[j].y),
                                  f2tf(fa[j].z), f2tf(fa[j].w));
            uint4 ub = make_uint4(f2tf(fb[j].x), f2tf(fb[j].y),
                                  f2tf(fb[j].z), f2tf(fb[j].w));
            *(uint4*)&sA[lr * GS + lc + 4 * j] = ua;
            *(uint4*)&sB[lr * GS + lc + 4 * j] = ub;
        }
        __syncthreads();

        if (it + 1 < 32) {
            const int kg = (it + 1) * 32;
            #pragma unroll
            for (int j = 0; j < 4; j++) {
                fa[j] = *(const float4*)(arow + kg + lc + 4 * j);
                fb[j] = *(const float4*)(brow + kg + lc + 4 * j);
            }
        }

        #pragma unroll
        for (int ks = 0; ks < 4; ks++) {
            const int ko = ks * 8;
            uint32_t af[2][4];
            #pragma unroll
            for (int mt = 0; mt < 2; mt++) {
                const int ab = aBase + mt * 16 * GS + ko;
                af[mt][0] = sA[ab];
                af[mt][1] = sA[ab + 8 * GS];
                af[mt][2] = sA[ab + 4];
                af[mt][3] = sA[ab + 8 * GS + 4];
            }
            uint32_t bf[8][2];
            #pragma unroll
            for (int nt = 0; nt < 8; nt++) {
                const int bb = bBase + nt * 8 * GS + ko;
                bf[nt][0] = sB[bb];
                bf[nt][1] = sB[bb + 4];
            }
            #pragma unroll
            for (int mt = 0; mt < 2; mt++)
                #pragma unroll
                for (int nt = 0; nt < 8; nt++)
                    mma_tf32(acc[mt][nt], af[mt][0], af[mt][1], af[mt][2],
                             af[mt][3], bf[nt][0], bf[nt][1]);
        }
    }

    const int erow = g;
    const int ecol = tg * 2;
    #pragma unroll
    for (int mt = 0; mt < 2; mt++) {
        const int row = bm + mw * 32 + mt * 16 + erow;
        #pragma unroll
        for (int nt = 0; nt < 8; nt++) {
            const int col = bn + nw * 64 + nt * 8 + ecol;
            const float c0 = __ldg(bias + col), c1 = __ldg(bias + col + 1);
            float2 lo, hi;
            lo.x = acc[mt][nt][0] + c0; lo.y = acc[mt][nt][1] + c1;
            hi.x = acc[mt][nt][2] + c0; hi.y = acc[mt][nt][3] + c1;
            *(float2*)(C + (size_t)row * 1024 + col)       = lo;
            *(float2*)(C + (size_t)(row + 8) * 1024 + col) = hi;
        }
    }
}

// ---------------------------------------------------------------------------
// Tensor-core flash attention (tf32 mma, explicit LDS fragments).
// Block: 128 queries x dh=64, 8 warps (warp w = query rows w*16..w*16+15).
// Softmax stats fully in registers (quad shuffles). P via warp-private smem.
// ---------------------------------------------------------------------------
#define AQ_STR 68       // Qs / Ps row stride (u32)  -> frag bank 4g+t
#define AK_STR 68       // Ks row stride
#define AV_STR 72       // Vs row stride             -> frag bank 8t+g
#define ATC_QS   0
#define ATC_KS   (128 * AQ_STR)                      // 8704
#define ATC_VS   (ATC_KS + 64 * AK_STR)              // 13056
#define ATC_PS   (ATC_VS + 64 * AV_STR)              // 17664
#define ATC_U32  (ATC_PS + 128 * AQ_STR)             // 26368
#define ATC_SMEM_BYTES (ATC_U32 * 4)                 // 105472

__global__ void __launch_bounds__(256) attn_tc()
{
    extern __shared__ uint32_t su[];
    uint32_t* Qs = su + ATC_QS;
    uint32_t* Ks = su + ATC_KS;
    uint32_t* Vs = su + ATC_VS;
    uint32_t* Ps = su + ATC_PS;

    const int tid = threadIdx.x;
    const int wid = tid >> 5;
    const int lan = tid & 31;
    const int g   = lan >> 2;
    const int t   = lan & 3;
    const int qt  = 7 - (int)blockIdx.x;     // reversed: big tiles first
    const int b   = blockIdx.y >> 4;
    const int h   = blockIdx.y & 15;
    const int q0  = qt * 128;
    const int mrow = wid * 16;

    // ---- load Q tile (128 x 64) as tf32 ----
    {
        const float* Qbase = g_Q + ((size_t)(b * LEN + q0)) * D_EMBED + h * DH;
        #pragma unroll
        for (int rep = 0; rep < 8; rep++) {
            const int li  = tid + rep * 256;
            const int row = li >> 4;
            const int c4  = (li & 15) << 2;
            float4 v = *(const float4*)(Qbase + (size_t)row * D_EMBED + c4);
            uint32_t* p = Qs + row * AQ_STR + c4;
            p[0] = f2tf(v.x); p[1] = f2tf(v.y);
            p[2] = f2tf(v.z); p[3] = f2tf(v.w);
        }
    }

    float ctx[8][4];
    #pragma unroll
    for (int dt = 0; dt < 8; dt++)
        #pragma unroll
        for (int e = 0; e < 4; e++) ctx[dt][e] = 0.f;
    float m0 = -1e30f, m1 = -1e30f, l0 = 0.f, l1 = 0.f;

    const int qrow0 = q0 + mrow + g;        // local-in-segment query positions
    const int qrow1 = qrow0 + 8;

    for (int seg = 0; seg < 3; seg++) {
        const float* Kbase = g_K + ((size_t)(b * SEQ_S + seg * LEN)) * D_EMBED + h * DH;
        const float* Vbase = g_V + ((size_t)(b * SEQ_S + seg * LEN)) * D_EMBED + h * DH;

        for (int kt = 0; kt < 2 * qt + 2; kt++) {
            const int s0 = kt * 64;
            __syncthreads();               // prior iter done with Ks/Vs (also orders Qs)
            #pragma unroll
            for (int rep = 0; rep < 4; rep++) {
                const int li  = tid + rep * 256;
                const int row = li >> 4;
                const int c4  = (li & 15) << 2;
                float4 kv = *(const float4*)(Kbase + (size_t)(s0 + row) * D_EMBED + c4);
                uint32_t* pk = Ks + row * AK_STR + c4;
                pk[0] = f2tf(kv.x); pk[1] = f2tf(kv.y);
                pk[2] = f2tf(kv.z); pk[3] = f2tf(kv.w);
                float4 vv = *(const float4*)(Vbase + (size_t)(s0 + row) * D_EMBED + c4);
                uint32_t* pv = Vs + row * AV_STR + c4;
                pv[0] = f2tf(vv.x); pv[1] = f2tf(vv.y);
                pv[2] = f2tf(vv.z); pv[3] = f2tf(vv.w);
            }
            __syncthreads();

            // ---- S = Q K^T (warp rows mrow..mrow+15 x 64 keys) ----
            float sf[8][4];
            #pragma unroll
            for (int nt = 0; nt < 8; nt++)
                #pragma unroll
                for (int e = 0; e < 4; e++) sf[nt][e] = 0.f;

            #pragma unroll
            for (int ks = 0; ks < 8; ks++) {
                const int ko = ks * 8;
                const uint32_t a0 = Qs[(mrow + g) * AQ_STR + ko + t];
                const uint32_t a1 = Qs[(mrow + g + 8) * AQ_STR + ko + t];
                const uint32_t a2 = Qs[(mrow + g) * AQ_STR + ko + t + 4];
                const uint32_t a3 = Qs[(mrow + g + 8) * AQ_STR + ko + t + 4];
                #pragma unroll
                for (int nt = 0; nt < 8; nt++) {
                    const int kr = (nt * 8 + g) * AK_STR + ko + t;
                    mma_tf32(sf[nt], a0, a1, a2, a3, Ks[kr], Ks[kr + 4]);
                }
            }

            // ---- scale + causal mask + row max (registers) ----
            float rmx0 = -1e30f, rmx1 = -1e30f;
            #pragma unroll
            for (int nt = 0; nt < 8; nt++) {
                const int c0 = s0 + nt * 8 + 2 * t;
                const int c1 = c0 + 1;
                float v0 = sf[nt][0] * 0.125f; if (c0 > qrow0) v0 = -1e30f;
                float v1 = sf[nt][1] * 0.125f; if (c1 > qrow0) v1 = -1e30f;
                float v2 = sf[nt][2] * 0.125f; if (c0 > qrow1) v2 = -1e30f;
                float v3 = sf[nt][3] * 0.125f; if (c1 > qrow1) v3 = -1e30f;
                sf[nt][0] = v0; sf[nt][1] = v1; sf[nt][2] = v2; sf[nt][3] = v3;
                rmx0 = fmaxf(rmx0, fmaxf(v0, v1));
                rmx1 = fmaxf(rmx1, fmaxf(v2, v3));
            }
            rmx0 = fmaxf(rmx0, __shfl_xor_sync(0xFFFFFFFFu, rmx0, 1));
            rmx0 = fmaxf(rmx0, __shfl_xor_sync(0xFFFFFFFFu, rmx0, 2));
            rmx1 = fmaxf(rmx1, __shfl_xor_sync(0xFFFFFFFFu, rmx1, 1));
            rmx1 = fmaxf(rmx1, __shfl_xor_sync(0xFFFFFFFFu, rmx1, 2));

            const float nm0 = fmaxf(m0, rmx0);
            const float nm1 = fmaxf(m1, rmx1);
            const float al0 = __expf(m0 - nm0);
            const float al1 = __expf(m1 - nm1);

            // ---- exp + row sum + stage P to smem (tf32) ----
            float rs0 = 0.f, rs1 = 0.f;
            #pragma unroll
            for (int nt = 0; nt < 8; nt++) {
                const float p0 = __expf(sf[nt][0] - nm0);
                const float p1 = __expf(sf[nt][1] - nm0);
                const float p2 = __expf(sf[nt][2] - nm1);
                const float p3 = __expf(sf[nt][3] - nm1);
                rs0 += p0 + p1;
                rs1 += p2 + p3;
                const int cc = nt * 8 + 2 * t;
                uint32_t* pr0 = Ps + (mrow + g) * AQ_STR + cc;
                uint32_t* pr1 = Ps + (mrow + g + 8) * AQ_STR + cc;
                pr0[0] = f2tf(p0); pr0[1] = f2tf(p1);
                pr1[0] = f2tf(p2); pr1[1] = f2tf(p3);
            }
            rs0 += __shfl_xor_sync(0xFFFFFFFFu, rs0, 1);
            rs0 += __shfl_xor_sync(0xFFFFFFFFu, rs0, 2);
            rs1 += __shfl_xor_sync(0xFFFFFFFFu, rs1, 1);
            rs1 += __shfl_xor_sync(0xFFFFFFFFu, rs1, 2);

            l0 = l0 * al0 + rs0; m0 = nm0;
            l1 = l1 * al1 + rs1; m1 = nm1;

            #pragma unroll
            for (int dt = 0; dt < 8; dt++) {
                ctx[dt][0] *= al0; ctx[dt][1] *= al0;
                ctx[dt][2] *= al1; ctx[dt][3] *= al1;
            }
            __syncwarp();                  // P visible to warp's A-frag loads

            // ---- ctx += P V ----
            #pragma unroll
            for (int ks = 0; ks < 8; ks++) {
                const int ko = ks * 8;
                const uint32_t a0 = Ps[(mrow + g) * AQ_STR + ko + t];
                const uint32_t a1 = Ps[(mrow + g + 8) * AQ_STR + ko + t];
                const uint32_t a2 = Ps[(mrow + g) * AQ_STR + ko + t + 4];
                const uint32_t a3 = Ps[(mrow + g + 8) * AQ_STR + ko + t + 4];
                #pragma unroll
                for (int dt = 0; dt < 8; dt++) {
                    const uint32_t b0 = Vs[(ko + t) * AV_STR + dt * 8 + g];
                    const uint32_t b1 = Vs[(ko + t + 4) * AV_STR + dt * 8 + g];
                    mma_tf32(ctx[dt], a0, a1, a2, a3, b0, b1);
                }
            }
            __syncwarp();                  // PV reads done before P rewrite
        }
    }

    // ---- epilogue ----
    const float inv0 = 1.f / l0;
    const float inv1 = 1.f / l1;
    float* o0 = g_CTX + ((size_t)(b * LEN + q0 + mrow + g)) * D_EMBED + h * DH;
    float* o1 = o0 + 8 * D_EMBED;
    #pragma unroll
    for (int dt = 0; dt < 8; dt++) {
        const int cc = dt * 8 + 2 * t;
        float2 w0, w1;
        w0.x = ctx[dt][0] * inv0; w0.y = ctx[dt][1] * inv0;
        w1.x = ctx[dt][2] * inv1; w1.y = ctx[dt][3] * inv1;
        *(float2*)(o0 + cc) = w0;
        *(float2*)(o1 + cc) = w1;
    }
}

// ---------------------------------------------------------------------------
// Residual + LayerNorm + mask epilogue — VERBATIM R1/R6
// ---------------------------------------------------------------------------
__global__ void __launch_bounds__(256) ln_mask_kernel(
    const float* __restrict__ hq, const float* __restrict__ lng,
    const float* __restrict__ lnb, const float* __restrict__ mask,
    float* __restrict__ out)
{
    __shared__ float red[32];
    const int row = blockIdx.x;
    const int tid = threadIdx.x;

    const float4 a = *(const float4*)(hq  + (size_t)row * D_EMBED + tid * 4);
    const float4 c = *(const float4*)(g_K + (size_t)row * D_EMBED + tid * 4);
    const float x0 = a.x + c.x, x1 = a.y + c.y, x2 = a.z + c.z, x3 = a.w + c.w;

    float s  = x0 + x1 + x2 + x3;
    float ss = x0 * x0 + x1 * x1 + x2 * x2 + x3 * x3;
    #pragma unroll
    for (int o = 16; o > 0; o >>= 1) {
        s  += __shfl_xor_sync(0xFFFFFFFFu, s,  o);
        ss += __shfl_xor_sync(0xFFFFFFFFu, ss, o);
    }
    const int w = tid >> 5;
    if ((tid & 31) == 0) { red[w] = s; red[w + 8] = ss; }
    __syncthreads();
    if (tid < 32) {
        float s2  = (tid < 8) ? red[tid]     : 0.f;
        float ss2 = (tid < 8) ? red[tid + 8] : 0.f;
        #pragma unroll
        for (int o = 4; o > 0; o >>= 1) {
            s2  += __shfl_xor_sync(0xFFFFFFFFu, s2,  o);
            ss2 += __shfl_xor_sync(0xFFFFFFFFu, ss2, o);
        }
        if (tid == 0) { red[16] = s2; red[17] = ss2; }
    }
    __syncthreads();

    const float mu   = red[16] * (1.f / 1024.f);
    const float var  = red[17] * (1.f / 1024.f) - mu * mu;
    const float rstd = rsqrtf(var + 1e-5f);
    const float mk   = mask[row];

    const float4 gg = *(const float4*)(lng + tid * 4);
    const float4 bb = *(const float4*)(lnb + tid * 4);
    float4 o;
    o.x = ((x0 - mu) * rstd * gg.x + bb.x) * mk;
    o.y = ((x1 - mu) * rstd * gg.y + bb.y) * mk;
    o.z = ((x2 - mu) * rstd * gg.z + bb.z) * mk;
    o.w = ((x3 - mu) * rstd * gg.w + bb.w) * mk;
    *(float4*)(out + (size_t)row * D_EMBED + tid * 4) = o;
}

// ---------------------------------------------------------------------------
extern "C" void kernel_launch(void* const* d_in, const int* in_sizes, int n_in,
                              void* d_out, int out_size)
{
    const float* h_q   = (const float*)d_in[0];
    const float* h_kv1 = (const float*)d_in[1];
    const float* h_kv2 = (const float*)d_in[2];
    const float* mask  = (const float*)d_in[3];
    const float* w_in  = (const float*)d_in[4];
    const float* b_in  = (const float*)d_in[5];
    const float* w_out = (const float*)d_in[6];
    const float* b_out = (const float*)d_in[7];
    const float* ln_g  = (const float*)d_in[8];
    const float* ln_b  = (const float*)d_in[9];
    float* out = (float*)d_out;

    cudaFuncSetAttribute(attn_tc,
                         cudaFuncAttributeMaxDynamicSharedMemorySize,
                         ATC_SMEM_BYTES);

    const dim3 gq(8, 16);   // N=1024/128, M=2048/128
    const dim3 gk(8, 48);   // M=6144/128

    // Q = h_q @ Wq^T + bq
    gemm_tf32<<<gq, 256>>>(h_q, nullptr, 0, w_in, b_in, 0);
    // K = concat(h_kv1,h_kv2) @ Wk^T + bk
    gemm_tf32<<<gk, 256>>>(h_kv1, h_kv2, 1, w_in + (size_t)1024 * 1024,
                           b_in + 1024, 1);
    // V
    gemm_tf32<<<gk, 256>>>(h_kv1, h_kv2, 1, w_in + (size_t)2048 * 1024,
                           b_in + 2048, 2);
    // attention -> g_CTX  (128-query tiles: 8 x B*H blocks)
    attn_tc<<<dim3(8, BATCH * N_HEAD), 256, ATC_SMEM_BYTES>>>();
    // attn_out = ctx @ out_w^T + out_b  (into g_K, now free)
    gemm_tf32<<<gq, 256>>>(nullptr, nullptr, 2, w_out, b_out, 1);
    // residual + LN + mask
    ln_mask_kernel<<<BATCH * LEN, 256>>>(h_q, ln_g, ln_b, mask, out);
}